// round 1
// baseline (speedup 1.0000x reference)
#include <cuda_runtime.h>
#include <math.h>

#define T_TOK   2048
#define HDIM    2048
#define NEXP    8
#define IDIM    5632
#define TWOI    11264
#define NASSIGN 4096
#define MAXTILES 40

#define BM 128
#define BN 128
#define BK 16

// ---------------- routing / scheduling state ----------------
__device__ int   g_perm_token[NASSIGN];
__device__ float g_perm_gate[NASSIGN];
__device__ int   g_sched_e[MAXTILES];
__device__ int   g_sched_row0[MAXTILES];
__device__ int   g_sched_rows[MAXTILES];

// ---------------- scratch (static device allocs are allowed) ----------------
__device__ float g_gu[(size_t)NASSIGN * TWOI];   // ~185 MB
__device__ float g_h [(size_t)NASSIGN * IDIM];   // ~92 MB

// ============================================================
// Routing: top-2 per token, per-expert buckets, tile schedule.
// Single block; T=2048 is tiny.
// ============================================================
__global__ void route_kernel(const float* __restrict__ logits)
{
    __shared__ int s_cnt[NEXP];
    __shared__ int s_off[NEXP + 1];
    __shared__ int s_cur[NEXP];
    const int tid = threadIdx.x;
    if (tid < NEXP) s_cnt[tid] = 0;
    __syncthreads();

    // pass 1: counts
    for (int t = tid; t < T_TOK; t += blockDim.x) {
        const float* l = logits + t * NEXP;
        int i1 = 0; float v1 = l[0];
        #pragma unroll
        for (int e = 1; e < NEXP; e++) { float v = l[e]; if (v > v1) { v1 = v; i1 = e; } }
        int i2 = -1; float v2 = -3.0e38f;
        #pragma unroll
        for (int e = 0; e < NEXP; e++) {
            if (e == i1) continue;
            float v = l[e]; if (v > v2) { v2 = v; i2 = e; }
        }
        atomicAdd(&s_cnt[i1], 1);
        atomicAdd(&s_cnt[i2], 1);
    }
    __syncthreads();

    if (tid == 0) {
        int acc = 0;
        for (int e = 0; e < NEXP; e++) { s_off[e] = acc; s_cur[e] = acc; acc += s_cnt[e]; }
        s_off[NEXP] = acc;
    }
    __syncthreads();

    // pass 2: scatter assignments
    for (int t = tid; t < T_TOK; t += blockDim.x) {
        const float* l = logits + t * NEXP;
        int i1 = 0; float v1 = l[0];
        #pragma unroll
        for (int e = 1; e < NEXP; e++) { float v = l[e]; if (v > v1) { v1 = v; i1 = e; } }
        int i2 = -1; float v2 = -3.0e38f;
        #pragma unroll
        for (int e = 0; e < NEXP; e++) {
            if (e == i1) continue;
            float v = l[e]; if (v > v2) { v2 = v; i2 = e; }
        }
        // softmax denominators cancel in the top-2 renormalization:
        // g1 = exp(l1)/(exp(l1)+exp(l2)) = 1/(1+exp(l2-l1)), l2 <= l1 (stable)
        float g1 = 1.0f / (1.0f + expf(v2 - v1));
        float g2 = 1.0f - g1;
        int s1 = atomicAdd(&s_cur[i1], 1);
        g_perm_token[s1] = t; g_perm_gate[s1] = g1;
        int s2 = atomicAdd(&s_cur[i2], 1);
        g_perm_token[s2] = t; g_perm_gate[s2] = g2;
    }
    __syncthreads();

    // tile schedule: fixed MAXTILES entries so GEMM grids can be static
    if (tid == 0) {
        int nt = 0;
        for (int e = 0; e < NEXP; e++) {
            int off = s_off[e], cnt = s_cnt[e];
            for (int r = 0; r < cnt; r += BM) {
                g_sched_e[nt]    = e;
                g_sched_row0[nt] = off + r;
                g_sched_rows[nt] = (cnt - r < BM) ? (cnt - r) : BM;
                nt++;
            }
        }
        for (; nt < MAXTILES; nt++) g_sched_rows[nt] = 0;
    }
}

// ============================================================
// zero the fp32 output
// ============================================================
__global__ void zero_kernel(float4* __restrict__ out)
{
    int idx = blockIdx.x * blockDim.x + threadIdx.x;
    if (idx < (T_TOK * HDIM) / 4) out[idx] = make_float4(0.f, 0.f, 0.f, 0.f);
}

// ============================================================
// GEMM1: gu[r, n] = sum_k X[token[r], k] * W13[e][n, k]
//   r: assignment row within expert segment, n in [0, 2I), k in [0, H)
// ============================================================
__global__ __launch_bounds__(256, 2) void gemm1_kernel(
    const float* __restrict__ X, const float* __restrict__ W13)
{
    const int bt    = blockIdx.y;
    const int mrows = g_sched_rows[bt];
    if (mrows == 0) return;
    const int e  = g_sched_e[bt];
    const int m0 = g_sched_row0[bt];
    const int n0 = blockIdx.x * BN;
    const float* Bmat = W13 + (size_t)e * TWOI * HDIM;

    __shared__ float As[BK][BM];
    __shared__ float Bs[BK][BN];

    const int tid  = threadIdx.x;
    const int tx   = tid & 15;
    const int ty   = tid >> 4;
    const int lrow = tid >> 2;         // 0..63
    const int lcol = (tid & 3) << 2;   // 0,4,8,12

    const int tokA0 = (lrow      < mrows) ? g_perm_token[m0 + lrow]      : -1;
    const int tokA1 = (lrow + 64 < mrows) ? g_perm_token[m0 + lrow + 64] : -1;
    const float* a0p = (tokA0 >= 0) ? X + (size_t)tokA0 * HDIM + lcol : 0;
    const float* a1p = (tokA1 >= 0) ? X + (size_t)tokA1 * HDIM + lcol : 0;
    const float* b0p = Bmat + (size_t)(n0 + lrow)      * HDIM + lcol;
    const float* b1p = Bmat + (size_t)(n0 + lrow + 64) * HDIM + lcol;

    float acc[8][8];
    #pragma unroll
    for (int i = 0; i < 8; i++)
        #pragma unroll
        for (int j = 0; j < 8; j++) acc[i][j] = 0.f;

    for (int k0 = 0; k0 < HDIM; k0 += BK) {
        float4 av0 = a0p ? *(const float4*)(a0p + k0) : make_float4(0.f,0.f,0.f,0.f);
        float4 av1 = a1p ? *(const float4*)(a1p + k0) : make_float4(0.f,0.f,0.f,0.f);
        float4 bv0 = *(const float4*)(b0p + k0);
        float4 bv1 = *(const float4*)(b1p + k0);
        __syncthreads();
        As[lcol+0][lrow]    = av0.x; As[lcol+1][lrow]    = av0.y;
        As[lcol+2][lrow]    = av0.z; As[lcol+3][lrow]    = av0.w;
        As[lcol+0][lrow+64] = av1.x; As[lcol+1][lrow+64] = av1.y;
        As[lcol+2][lrow+64] = av1.z; As[lcol+3][lrow+64] = av1.w;
        Bs[lcol+0][lrow]    = bv0.x; Bs[lcol+1][lrow]    = bv0.y;
        Bs[lcol+2][lrow]    = bv0.z; Bs[lcol+3][lrow]    = bv0.w;
        Bs[lcol+0][lrow+64] = bv1.x; Bs[lcol+1][lrow+64] = bv1.y;
        Bs[lcol+2][lrow+64] = bv1.z; Bs[lcol+3][lrow+64] = bv1.w;
        __syncthreads();
        #pragma unroll
        for (int kk = 0; kk < BK; kk++) {
            float a[8], b[8];
            *(float4*)&a[0] = *(const float4*)&As[kk][ty*8];
            *(float4*)&a[4] = *(const float4*)&As[kk][ty*8+4];
            *(float4*)&b[0] = *(const float4*)&Bs[kk][tx*8];
            *(float4*)&b[4] = *(const float4*)&Bs[kk][tx*8+4];
            #pragma unroll
            for (int i = 0; i < 8; i++)
                #pragma unroll
                for (int j = 0; j < 8; j++)
                    acc[i][j] = fmaf(a[i], b[j], acc[i][j]);
        }
    }

    #pragma unroll
    for (int i = 0; i < 8; i++) {
        int r = ty*8 + i;
        if (r < mrows) {
            float* dst = g_gu + (size_t)(m0 + r) * TWOI + n0 + tx*8;
            *(float4*)(dst)     = *(float4*)&acc[i][0];
            *(float4*)(dst + 4) = *(float4*)&acc[i][4];
        }
    }
}

// ============================================================
// Activation: h = silu(g) * u   (every assignment row is valid)
// ============================================================
__global__ void act_kernel()
{
    size_t idx4 = (size_t)blockIdx.x * blockDim.x + threadIdx.x;
    const size_t n4 = (size_t)NASSIGN * IDIM / 4;
    if (idx4 >= n4) return;
    size_t idx = idx4 * 4;
    size_t r = idx / IDIM;
    size_t c = idx % IDIM;
    const float4 g = *(const float4*)(g_gu + r * TWOI + c);
    const float4 u = *(const float4*)(g_gu + r * TWOI + IDIM + c);
    float4 h;
    h.x = g.x / (1.0f + expf(-g.x)) * u.x;
    h.y = g.y / (1.0f + expf(-g.y)) * u.y;
    h.z = g.z / (1.0f + expf(-g.z)) * u.z;
    h.w = g.w / (1.0f + expf(-g.w)) * u.w;
    *(float4*)(g_h + idx) = h;
}

// ============================================================
// GEMM2: out[token[r], n] += gate[r] * sum_k h[r, k] * W2[e][n, k]
//   n in [0, H), k in [0, I)
// ============================================================
__global__ __launch_bounds__(256, 2) void gemm2_kernel(
    const float* __restrict__ W2, float* __restrict__ out)
{
    const int bt    = blockIdx.y;
    const int mrows = g_sched_rows[bt];
    if (mrows == 0) return;
    const int e  = g_sched_e[bt];
    const int m0 = g_sched_row0[bt];
    const int n0 = blockIdx.x * BN;
    const float* Bmat = W2 + (size_t)e * HDIM * IDIM;

    __shared__ float As[BK][BM];
    __shared__ float Bs[BK][BN];

    const int tid  = threadIdx.x;
    const int tx   = tid & 15;
    const int ty   = tid >> 4;
    const int lrow = tid >> 2;
    const int lcol = (tid & 3) << 2;

    const float* a0p = (lrow      < mrows) ? g_h + (size_t)(m0 + lrow)      * IDIM + lcol : 0;
    const float* a1p = (lrow + 64 < mrows) ? g_h + (size_t)(m0 + lrow + 64) * IDIM + lcol : 0;
    const float* b0p = Bmat + (size_t)(n0 + lrow)      * IDIM + lcol;
    const float* b1p = Bmat + (size_t)(n0 + lrow + 64) * IDIM + lcol;

    float acc[8][8];
    #pragma unroll
    for (int i = 0; i < 8; i++)
        #pragma unroll
        for (int j = 0; j < 8; j++) acc[i][j] = 0.f;

    for (int k0 = 0; k0 < IDIM; k0 += BK) {
        float4 av0 = a0p ? *(const float4*)(a0p + k0) : make_float4(0.f,0.f,0.f,0.f);
        float4 av1 = a1p ? *(const float4*)(a1p + k0) : make_float4(0.f,0.f,0.f,0.f);
        float4 bv0 = *(const float4*)(b0p + k0);
        float4 bv1 = *(const float4*)(b1p + k0);
        __syncthreads();
        As[lcol+0][lrow]    = av0.x; As[lcol+1][lrow]    = av0.y;
        As[lcol+2][lrow]    = av0.z; As[lcol+3][lrow]    = av0.w;
        As[lcol+0][lrow+64] = av1.x; As[lcol+1][lrow+64] = av1.y;
        As[lcol+2][lrow+64] = av1.z; As[lcol+3][lrow+64] = av1.w;
        Bs[lcol+0][lrow]    = bv0.x; Bs[lcol+1][lrow]    = bv0.y;
        Bs[lcol+2][lrow]    = bv0.z; Bs[lcol+3][lrow]    = bv0.w;
        Bs[lcol+0][lrow+64] = bv1.x; Bs[lcol+1][lrow+64] = bv1.y;
        Bs[lcol+2][lrow+64] = bv1.z; Bs[lcol+3][lrow+64] = bv1.w;
        __syncthreads();
        #pragma unroll
        for (int kk = 0; kk < BK; kk++) {
            float a[8], b[8];
            *(float4*)&a[0] = *(const float4*)&As[kk][ty*8];
            *(float4*)&a[4] = *(const float4*)&As[kk][ty*8+4];
            *(float4*)&b[0] = *(const float4*)&Bs[kk][tx*8];
            *(float4*)&b[4] = *(const float4*)&Bs[kk][tx*8+4];
            #pragma unroll
            for (int i = 0; i < 8; i++)
                #pragma unroll
                for (int j = 0; j < 8; j++)
                    acc[i][j] = fmaf(a[i], b[j], acc[i][j]);
        }
    }

    #pragma unroll
    for (int i = 0; i < 8; i++) {
        int r = ty*8 + i;
        if (r < mrows) {
            const int   tok  = g_perm_token[m0 + r];
            const float gate = g_perm_gate[m0 + r];
            float* dst = out + (size_t)tok * HDIM + n0 + tx*8;
            #pragma unroll
            for (int j = 0; j < 8; j++)
                atomicAdd(dst + j, gate * acc[i][j]);
        }
    }
}

// ============================================================
// launch
// ============================================================
extern "C" void kernel_launch(void* const* d_in, const int* in_sizes, int n_in,
                              void* d_out, int out_size)
{
    const float* hs     = (const float*)d_in[0];  // (T, H) fp32
    const float* logits = (const float*)d_in[1];  // (T, E) fp32
    const float* w13    = (const float*)d_in[2];  // (E, 2I, H) fp32
    const float* w2     = (const float*)d_in[3];  // (E, H, I) fp32
    float* out = (float*)d_out;                   // (T, H) fp32

    zero_kernel<<<(T_TOK * HDIM / 4 + 255) / 256, 256>>>((float4*)out);
    route_kernel<<<1, 256>>>(logits);

    dim3 g1(TWOI / BN, MAXTILES);
    gemm1_kernel<<<g1, 256>>>(hs, w13);

    size_t n4 = (size_t)NASSIGN * IDIM / 4;
    act_kernel<<<(unsigned)((n4 + 255) / 256), 256>>>();

    dim3 g2(HDIM / BN, MAXTILES);
    gemm2_kernel<<<g2, 256>>>(w2, out);
}

// round 6
// speedup vs baseline: 1.8495x; 1.8495x over previous
#include <cuda_runtime.h>
#include <cuda_bf16.h>
#include <math.h>
#include <stdint.h>

#define T_TOK   2048
#define HDIM    2048
#define NEXP    8
#define IDIM    5632
#define TWOI    11264
#define NASSIGN 4096
#define MAXT    40
#define PADROWS (NASSIGN + 256)

#define BM 128
#define BN 256
#define BK 32
#define PITCH 40                        // bf16 elems per smem row (80B) — conflict-free
#define ASZ (BM * PITCH * 2)            // 10240 B
#define BSZ (BN * PITCH * 2)            // 20480 B
#define STAGE (ASZ + BSZ)               // 30720 B
#define SMEM_BYTES (2 * STAGE)          // 61440 B

// ---------------- routing / scheduling state ----------------
__device__ int   g_perm_token[NASSIGN];
__device__ float g_perm_gate[NASSIGN];
__device__ int   g_se[MAXT], g_sm0[MAXT], g_srows[MAXT];

// ---------------- converted operands / scratch ----------------
__device__ __align__(128) __nv_bfloat16 g_ah[(size_t)PADROWS * HDIM];
__device__ __align__(128) __nv_bfloat16 g_al[(size_t)PADROWS * HDIM];
__device__ __align__(128) __nv_bfloat16 g_w13h[(size_t)NEXP * TWOI * HDIM];
__device__ __align__(128) __nv_bfloat16 g_w13l[(size_t)NEXP * TWOI * HDIM];
__device__ __align__(128) __nv_bfloat16 g_w2h[(size_t)NEXP * HDIM * IDIM];
__device__ __align__(128) __nv_bfloat16 g_w2l[(size_t)NEXP * HDIM * IDIM];
__device__ __align__(128) float         g_gu[(size_t)NASSIGN * TWOI];
__device__ __align__(128) __nv_bfloat16 g_hh[(size_t)PADROWS * IDIM];
__device__ __align__(128) __nv_bfloat16 g_hl[(size_t)PADROWS * IDIM];

// ================= helpers =================
__device__ __forceinline__ uint32_t smem_to_u32(const void* p) {
    uint32_t a;
    asm("{ .reg .u64 t; cvta.to.shared.u64 t, %1; cvt.u32.u64 %0, t; }" : "=r"(a) : "l"(p));
    return a;
}
__device__ __forceinline__ void cp16(uint32_t dst, const void* src) {
    asm volatile("cp.async.cg.shared.global [%0], [%1], 16;" :: "r"(dst), "l"(src));
}
__device__ __forceinline__ void ldsm4(uint32_t* r, uint32_t addr) {
    asm volatile("ldmatrix.sync.aligned.m8n8.x4.shared.b16 {%0,%1,%2,%3}, [%4];"
                 : "=r"(r[0]), "=r"(r[1]), "=r"(r[2]), "=r"(r[3]) : "r"(addr));
}
__device__ __forceinline__ void mma16816(float* d, const uint32_t* a, const uint32_t* b) {
    asm volatile(
        "mma.sync.aligned.m16n8k16.row.col.f32.bf16.bf16.f32 "
        "{%0,%1,%2,%3}, {%4,%5,%6,%7}, {%8,%9}, {%0,%1,%2,%3};"
        : "+f"(d[0]), "+f"(d[1]), "+f"(d[2]), "+f"(d[3])
        : "r"(a[0]), "r"(a[1]), "r"(a[2]), "r"(a[3]), "r"(b[0]), "r"(b[1]));
}

// ================= routing =================
__global__ void route_kernel(const float* __restrict__ logits)
{
    __shared__ int s_cnt[NEXP], s_off[NEXP + 1], s_cur[NEXP];
    const int tid = threadIdx.x;
    if (tid < NEXP) s_cnt[tid] = 0;
    __syncthreads();
    for (int t = tid; t < T_TOK; t += blockDim.x) {
        const float* l = logits + t * NEXP;
        int i1 = 0; float v1 = l[0];
        #pragma unroll
        for (int e = 1; e < NEXP; e++) { float v = l[e]; if (v > v1) { v1 = v; i1 = e; } }
        int i2 = -1; float v2 = -3.0e38f;
        #pragma unroll
        for (int e = 0; e < NEXP; e++) { if (e == i1) continue; float v = l[e]; if (v > v2) { v2 = v; i2 = e; } }
        atomicAdd(&s_cnt[i1], 1); atomicAdd(&s_cnt[i2], 1);
    }
    __syncthreads();
    if (tid == 0) {
        int acc = 0;
        for (int e = 0; e < NEXP; e++) { s_off[e] = acc; s_cur[e] = acc; acc += s_cnt[e]; }
        s_off[NEXP] = acc;
    }
    __syncthreads();
    for (int t = tid; t < T_TOK; t += blockDim.x) {
        const float* l = logits + t * NEXP;
        int i1 = 0; float v1 = l[0];
        #pragma unroll
        for (int e = 1; e < NEXP; e++) { float v = l[e]; if (v > v1) { v1 = v; i1 = e; } }
        int i2 = -1; float v2 = -3.0e38f;
        #pragma unroll
        for (int e = 0; e < NEXP; e++) { if (e == i1) continue; float v = l[e]; if (v > v2) { v2 = v; i2 = e; } }
        float g1 = 1.0f / (1.0f + expf(v2 - v1));
        float g2 = 1.0f - g1;
        int s1 = atomicAdd(&s_cur[i1], 1);
        g_perm_token[s1] = t; g_perm_gate[s1] = g1;
        int s2 = atomicAdd(&s_cur[i2], 1);
        g_perm_token[s2] = t; g_perm_gate[s2] = g2;
    }
    __syncthreads();
    if (tid == 0) {
        int nt = 0;
        for (int e = 0; e < NEXP; e++) {
            int off = s_off[e], cnt = s_cnt[e];
            for (int r = 0; r < cnt; r += BM) {
                g_se[nt] = e; g_sm0[nt] = off + r;
                g_srows[nt] = (cnt - r < BM) ? (cnt - r) : BM; nt++;
            }
        }
        for (; nt < MAXT; nt++) g_srows[nt] = 0;
    }
}

__global__ void zero_kernel(float4* __restrict__ out)
{
    int idx = blockIdx.x * blockDim.x + threadIdx.x;
    if (idx < (T_TOK * HDIM) / 4) out[idx] = make_float4(0.f, 0.f, 0.f, 0.f);
}

// gather+split X rows into permuted bf16 hi/lo (globals referenced in device code)
__global__ void permA_kernel(const float* __restrict__ X)
{
    int idx = blockIdx.x * blockDim.x + threadIdx.x;
    if (idx >= NASSIGN * HDIM / 4) return;
    int r = idx / (HDIM / 4);
    int c = (idx % (HDIM / 4)) * 4;
    int t = g_perm_token[r];
    float4 x = *(const float4*)(X + (size_t)t * HDIM + c);
    __nv_bfloat16 h0 = __float2bfloat16(x.x), h1 = __float2bfloat16(x.y);
    __nv_bfloat16 h2 = __float2bfloat16(x.z), h3 = __float2bfloat16(x.w);
    __nv_bfloat16 l0 = __float2bfloat16(x.x - __bfloat162float(h0));
    __nv_bfloat16 l1 = __float2bfloat16(x.y - __bfloat162float(h1));
    __nv_bfloat16 l2 = __float2bfloat16(x.z - __bfloat162float(h2));
    __nv_bfloat16 l3 = __float2bfloat16(x.w - __bfloat162float(h3));
    size_t o = (size_t)r * HDIM + c;
    *(__nv_bfloat162*)(g_ah + o)     = __nv_bfloat162(h0, h1);
    *(__nv_bfloat162*)(g_ah + o + 2) = __nv_bfloat162(h2, h3);
    *(__nv_bfloat162*)(g_al + o)     = __nv_bfloat162(l0, l1);
    *(__nv_bfloat162*)(g_al + o + 2) = __nv_bfloat162(l2, l3);
}

// split fp32 weights into bf16 hi/lo. WHICH: 0 = w13, 1 = w2.
// Device globals selected INSIDE device code (never passed from host).
template<int WHICH>
__global__ void cvt_kernel(const float4* __restrict__ src, size_t n4)
{
    __nv_bfloat16* hi = (WHICH == 0) ? g_w13h : g_w2h;
    __nv_bfloat16* lo = (WHICH == 0) ? g_w13l : g_w2l;
    size_t idx = (size_t)blockIdx.x * blockDim.x + threadIdx.x;
    if (idx >= n4) return;
    float4 x = src[idx];
    __nv_bfloat16 h0 = __float2bfloat16(x.x), h1 = __float2bfloat16(x.y);
    __nv_bfloat16 h2 = __float2bfloat16(x.z), h3 = __float2bfloat16(x.w);
    __nv_bfloat16 l0 = __float2bfloat16(x.x - __bfloat162float(h0));
    __nv_bfloat16 l1 = __float2bfloat16(x.y - __bfloat162float(h1));
    __nv_bfloat16 l2 = __float2bfloat16(x.z - __bfloat162float(h2));
    __nv_bfloat16 l3 = __float2bfloat16(x.w - __bfloat162float(h3));
    size_t o = idx * 4;
    *(__nv_bfloat162*)(hi + o)     = __nv_bfloat162(h0, h1);
    *(__nv_bfloat162*)(hi + o + 2) = __nv_bfloat162(h2, h3);
    *(__nv_bfloat162*)(lo + o)     = __nv_bfloat162(l0, l1);
    *(__nv_bfloat162*)(lo + o + 2) = __nv_bfloat162(l2, l3);
}

// h = silu(g)*u, split into bf16 hi/lo
__global__ void act_kernel()
{
    size_t idx = (size_t)blockIdx.x * blockDim.x + threadIdx.x;
    if (idx >= (size_t)NASSIGN * IDIM / 4) return;
    size_t r = idx / (IDIM / 4);
    size_t c = (idx % (IDIM / 4)) * 4;
    const float4 g = *(const float4*)(g_gu + r * TWOI + c);
    const float4 u = *(const float4*)(g_gu + r * TWOI + IDIM + c);
    float4 h;
    h.x = g.x / (1.0f + expf(-g.x)) * u.x;
    h.y = g.y / (1.0f + expf(-g.y)) * u.y;
    h.z = g.z / (1.0f + expf(-g.z)) * u.z;
    h.w = g.w / (1.0f + expf(-g.w)) * u.w;
    __nv_bfloat16 h0 = __float2bfloat16(h.x), h1 = __float2bfloat16(h.y);
    __nv_bfloat16 h2 = __float2bfloat16(h.z), h3 = __float2bfloat16(h.w);
    __nv_bfloat16 l0 = __float2bfloat16(h.x - __bfloat162float(h0));
    __nv_bfloat16 l1 = __float2bfloat16(h.y - __bfloat162float(h1));
    __nv_bfloat16 l2 = __float2bfloat16(h.z - __bfloat162float(h2));
    __nv_bfloat16 l3 = __float2bfloat16(h.w - __bfloat162float(h3));
    size_t o = r * IDIM + c;
    *(__nv_bfloat162*)(g_hh + o)     = __nv_bfloat162(h0, h1);
    *(__nv_bfloat162*)(g_hh + o + 2) = __nv_bfloat162(h2, h3);
    *(__nv_bfloat162*)(g_hl + o)     = __nv_bfloat162(l0, l1);
    *(__nv_bfloat162*)(g_hl + o + 2) = __nv_bfloat162(l2, l3);
}

// ================= mma.sync GEMM: 128x256 tile, split-bf16 x3 =================
template<int KD>
__device__ __forceinline__ void load_stage(uint32_t sbase, int tid,
    const __nv_bfloat16* __restrict__ A, const __nv_bfloat16* __restrict__ B,
    int m0, int n0, int kk)
{
    {   // A: 128 rows x 32 k = 512 x 16B chunks, one per thread
        int row = tid >> 2, kg = tid & 3;
        cp16(sbase + (row * PITCH + kg * 8) * 2,
             A + (size_t)(m0 + row) * KD + kk + kg * 8);
    }
    {   // B: 256 rows x 32 k = 1024 chunks, two per thread
        uint32_t bb = sbase + ASZ;
        #pragma unroll
        for (int j = 0; j < 2; j++) {
            int idx = j * 512 + tid;
            int row = idx >> 2, kg = idx & 3;
            cp16(bb + (row * PITCH + kg * 8) * 2,
                 B + (size_t)(n0 + row) * KD + kk + kg * 8);
        }
    }
    asm volatile("cp.async.commit_group;" ::: "memory");
}

// EPI: 1 = GEMM1 (A = g_ah/g_al, B = g_w13h/l, write g_gu)
//      2 = GEMM2 (A = g_hh/g_hl, B = g_w2h/l,  gated atomicAdd to out)
template<int KD, int NTOT, int EPI>
__global__ __launch_bounds__(512, 1) void gemm_mma(float* __restrict__ outp)
{
    constexpr int KCH = KD / BK;
    constexpr int NCH = 3 * KCH;

    const int bt    = blockIdx.x;
    const int mrows = g_srows[bt];
    if (mrows == 0) return;
    const int e  = g_se[bt];
    const int m0 = g_sm0[bt];
    const int n0 = blockIdx.y * BN;

    // operand arrays selected in DEVICE code — real device addresses
    const __nv_bfloat16* Ah = (EPI == 1) ? g_ah : g_hh;
    const __nv_bfloat16* Al = (EPI == 1) ? g_al : g_hl;
    const __nv_bfloat16* Bh = ((EPI == 1) ? g_w13h : g_w2h) + (size_t)e * NTOT * KD;
    const __nv_bfloat16* Bl = ((EPI == 1) ? g_w13l : g_w2l) + (size_t)e * NTOT * KD;

    extern __shared__ char smem[];
    const uint32_t sb0 = smem_to_u32(smem);
    const int tid  = threadIdx.x;
    const int wid  = tid >> 5;
    const int lane = tid & 31;
    const int wm   = (wid & 3) << 5;   // warp M offset (0..96)
    const int wn   = (wid >> 2) << 6;  // warp N offset (0..192)

    float acc[2][8][4];
    #pragma unroll
    for (int i = 0; i < 2; i++)
        #pragma unroll
        for (int j = 0; j < 8; j++)
            #pragma unroll
            for (int q = 0; q < 4; q++) acc[i][j][q] = 0.f;

    // ldmatrix per-lane addresses (byte offsets within a stage)
    const uint32_t a_off = ((wm + (lane & 15)) * PITCH + ((lane >> 4) << 3)) * 2;
    const uint32_t b_off = ASZ + ((wn + ((lane >> 4) << 3) + (lane & 7)) * PITCH + (((lane >> 3) & 1) << 3)) * 2;

    load_stage<KD>(sb0, tid, Ah, Bh, m0, n0, 0);

    for (int i = 0; i < NCH; i++) {
        const int b = i & 1;
        if (i + 1 < NCH) {
            const int nc = i + 1;
            const int term = nc / KCH, kk = (nc - term * KCH) * BK;
            const __nv_bfloat16* A = (term == 1) ? Al : Ah;
            const __nv_bfloat16* B = (term == 2) ? Bl : Bh;
            load_stage<KD>(sb0 + (1 - b) * STAGE, tid, A, B, m0, n0, kk);
            asm volatile("cp.async.wait_group 1;" ::: "memory");
        } else {
            asm volatile("cp.async.wait_group 0;" ::: "memory");
        }
        __syncthreads();

        const uint32_t sa = sb0 + b * STAGE;
        #pragma unroll
        for (int ks = 0; ks < BK; ks += 16) {
            uint32_t afr[2][4], bfr[4][4];
            ldsm4(afr[0], sa + a_off + ks * 2);
            ldsm4(afr[1], sa + a_off + (16 * PITCH + ks) * 2);
            #pragma unroll
            for (int jn = 0; jn < 4; jn++)
                ldsm4(bfr[jn], sa + b_off + (jn * 16 * PITCH + ks) * 2);
            #pragma unroll
            for (int im = 0; im < 2; im++)
                #pragma unroll
                for (int jn = 0; jn < 4; jn++) {
                    mma16816(acc[im][2 * jn],     afr[im], &bfr[jn][0]);
                    mma16816(acc[im][2 * jn + 1], afr[im], &bfr[jn][2]);
                }
        }
        __syncthreads();
    }

    // ---------------- epilogue ----------------
    #pragma unroll
    for (int im = 0; im < 2; im++) {
        #pragma unroll
        for (int half = 0; half < 2; half++) {
            const int rloc = wm + im * 16 + half * 8 + (lane >> 2);
            const bool v = (rloc < mrows);
            int tok = 0; float gate = 0.f;
            if (EPI == 2 && v) {
                tok  = g_perm_token[m0 + rloc];
                gate = g_perm_gate[m0 + rloc];
            }
            #pragma unroll
            for (int jn8 = 0; jn8 < 8; jn8++) {
                const float d0 = acc[im][jn8][half * 2 + 0];
                const float d1 = acc[im][jn8][half * 2 + 1];
                const int col = n0 + wn + jn8 * 8 + ((lane & 3) << 1);
                if (v) {
                    if (EPI == 1) {
                        float2* dst = (float2*)(g_gu + (size_t)(m0 + rloc) * TWOI + col);
                        *dst = make_float2(d0, d1);
                    } else {
                        float* dst = outp + (size_t)tok * HDIM + col;
                        atomicAdd(dst + 0, gate * d0);
                        atomicAdd(dst + 1, gate * d1);
                    }
                }
            }
        }
    }
}

// ================= launch =================
extern "C" void kernel_launch(void* const* d_in, const int* in_sizes, int n_in,
                              void* d_out, int out_size)
{
    const float* hs     = (const float*)d_in[0];
    const float* logits = (const float*)d_in[1];
    const float* w13    = (const float*)d_in[2];
    const float* w2     = (const float*)d_in[3];
    float* out = (float*)d_out;

    cudaFuncSetAttribute(gemm_mma<HDIM, TWOI, 1>, cudaFuncAttributeMaxDynamicSharedMemorySize, SMEM_BYTES);
    cudaFuncSetAttribute(gemm_mma<IDIM, HDIM, 2>, cudaFuncAttributeMaxDynamicSharedMemorySize, SMEM_BYTES);

    zero_kernel<<<(T_TOK * HDIM / 4 + 255) / 256, 256>>>((float4*)out);
    route_kernel<<<1, 256>>>(logits);
    permA_kernel<<<(NASSIGN * HDIM / 4 + 255) / 256, 256>>>(hs);

    size_t n4_w13 = (size_t)NEXP * TWOI * HDIM / 4;
    size_t n4_w2  = (size_t)NEXP * HDIM * IDIM / 4;
    cvt_kernel<0><<<(unsigned)((n4_w13 + 255) / 256), 256>>>((const float4*)w13, n4_w13);
    cvt_kernel<1><<<(unsigned)((n4_w2  + 255) / 256), 256>>>((const float4*)w2,  n4_w2);

    gemm_mma<HDIM, TWOI, 1><<<dim3(MAXT, TWOI / BN), 512, SMEM_BYTES>>>(nullptr);

    size_t nact = (size_t)NASSIGN * IDIM / 4;
    act_kernel<<<(unsigned)((nact + 255) / 256), 256>>>();

    gemm_mma<IDIM, HDIM, 2><<<dim3(MAXT, HDIM / BN), 512, SMEM_BYTES>>>(out);
}

// round 7
// speedup vs baseline: 2.3624x; 1.2773x over previous
#include <cuda_runtime.h>
#include <cuda_bf16.h>
#include <math.h>
#include <stdint.h>

#define T_TOK   2048
#define HDIM    2048
#define NEXP    8
#define IDIM    5632
#define TWOI    11264
#define NASSIGN 4096
#define MAXT    40
#define PADROWS (NASSIGN + 256)

#define BM 128
#define BN 256
#define BK 32
#define PITCH 40          // bf16 elems per tile row (80B)

// smem layout (bytes)
#define AH_OFF 0
#define AL_OFF 10240
#define BH_OFF 20480
#define BL_OFF 40960
#define FA_OFF 61440      // fp32 staging A: 128 rows x 144B
#define FB_OFF 79872      // fp32 staging B: 256 rows x 144B
#define FPITCHB 144
#define SMEM_BYTES 116736

// ---------------- routing / scheduling state ----------------
__device__ int   g_perm_token[NASSIGN];
__device__ float g_perm_gate[NASSIGN];
__device__ int   g_se[MAXT], g_sm0[MAXT], g_srows[MAXT];

// ---------------- scratch ----------------
__device__ __align__(128) float g_gu[(size_t)NASSIGN * TWOI];
__device__ __align__(128) float g_h [(size_t)PADROWS * IDIM];

// ================= helpers =================
__device__ __forceinline__ uint32_t smem_to_u32(const void* p) {
    uint32_t a;
    asm("{ .reg .u64 t; cvta.to.shared.u64 t, %1; cvt.u32.u64 %0, t; }" : "=r"(a) : "l"(p));
    return a;
}
__device__ __forceinline__ void cp16(uint32_t dst, const void* src) {
    asm volatile("cp.async.cg.shared.global [%0], [%1], 16;" :: "r"(dst), "l"(src));
}
__device__ __forceinline__ void ldsm4(uint32_t* r, uint32_t addr) {
    asm volatile("ldmatrix.sync.aligned.m8n8.x4.shared.b16 {%0,%1,%2,%3}, [%4];"
                 : "=r"(r[0]), "=r"(r[1]), "=r"(r[2]), "=r"(r[3]) : "r"(addr));
}
__device__ __forceinline__ void mma16816(float* d, const uint32_t* a, const uint32_t* b) {
    asm volatile(
        "mma.sync.aligned.m16n8k16.row.col.f32.bf16.bf16.f32 "
        "{%0,%1,%2,%3}, {%4,%5,%6,%7}, {%8,%9}, {%0,%1,%2,%3};"
        : "+f"(d[0]), "+f"(d[1]), "+f"(d[2]), "+f"(d[3])
        : "r"(a[0]), "r"(a[1]), "r"(a[2]), "r"(a[3]), "r"(b[0]), "r"(b[1]));
}
__device__ __forceinline__ void lds128(float4& v, uint32_t a) {
    asm volatile("ld.shared.v4.f32 {%0,%1,%2,%3}, [%4];"
                 : "=f"(v.x), "=f"(v.y), "=f"(v.z), "=f"(v.w) : "r"(a));
}
__device__ __forceinline__ void sts128(uint32_t a, uint32_t x, uint32_t y, uint32_t z, uint32_t w) {
    asm volatile("st.shared.v4.b32 [%0], {%1,%2,%3,%4};" :: "r"(a), "r"(x), "r"(y), "r"(z), "r"(w));
}
// split fp32 pair -> bf16x2 hi + bf16x2 lo (packed u32)
__device__ __forceinline__ void split2(float f0, float f1, uint32_t& h, uint32_t& l) {
    __nv_bfloat162 hh = __floats2bfloat162_rn(f0, f1);
    float r0 = f0 - __bfloat162float(hh.x);
    float r1 = f1 - __bfloat162float(hh.y);
    __nv_bfloat162 ll = __floats2bfloat162_rn(r0, r1);
    h = *(uint32_t*)&hh; l = *(uint32_t*)&ll;
}

// ================= routing =================
__global__ void route_kernel(const float* __restrict__ logits)
{
    __shared__ int s_cnt[NEXP], s_off[NEXP + 1], s_cur[NEXP];
    const int tid = threadIdx.x;
    if (tid < NEXP) s_cnt[tid] = 0;
    __syncthreads();
    for (int t = tid; t < T_TOK; t += blockDim.x) {
        const float* l = logits + t * NEXP;
        int i1 = 0; float v1 = l[0];
        #pragma unroll
        for (int e = 1; e < NEXP; e++) { float v = l[e]; if (v > v1) { v1 = v; i1 = e; } }
        int i2 = -1; float v2 = -3.0e38f;
        #pragma unroll
        for (int e = 0; e < NEXP; e++) { if (e == i1) continue; float v = l[e]; if (v > v2) { v2 = v; i2 = e; } }
        atomicAdd(&s_cnt[i1], 1); atomicAdd(&s_cnt[i2], 1);
    }
    __syncthreads();
    if (tid == 0) {
        int acc = 0;
        for (int e = 0; e < NEXP; e++) { s_off[e] = acc; s_cur[e] = acc; acc += s_cnt[e]; }
        s_off[NEXP] = acc;
    }
    __syncthreads();
    for (int t = tid; t < T_TOK; t += blockDim.x) {
        const float* l = logits + t * NEXP;
        int i1 = 0; float v1 = l[0];
        #pragma unroll
        for (int e = 1; e < NEXP; e++) { float v = l[e]; if (v > v1) { v1 = v; i1 = e; } }
        int i2 = -1; float v2 = -3.0e38f;
        #pragma unroll
        for (int e = 0; e < NEXP; e++) { if (e == i1) continue; float v = l[e]; if (v > v2) { v2 = v; i2 = e; } }
        float g1 = 1.0f / (1.0f + expf(v2 - v1));
        float g2 = 1.0f - g1;
        int s1 = atomicAdd(&s_cur[i1], 1);
        g_perm_token[s1] = t; g_perm_gate[s1] = g1;
        int s2 = atomicAdd(&s_cur[i2], 1);
        g_perm_token[s2] = t; g_perm_gate[s2] = g2;
    }
    __syncthreads();
    if (tid == 0) {
        int nt = 0;
        for (int e = 0; e < NEXP; e++) {
            int off = s_off[e], cnt = s_cnt[e];
            for (int r = 0; r < cnt; r += BM) {
                g_se[nt] = e; g_sm0[nt] = off + r;
                g_srows[nt] = (cnt - r < BM) ? (cnt - r) : BM; nt++;
            }
        }
        for (; nt < MAXT; nt++) g_srows[nt] = 0;
    }
}

__global__ void zero_kernel(float4* __restrict__ out)
{
    int idx = blockIdx.x * blockDim.x + threadIdx.x;
    if (idx < (T_TOK * HDIM) / 4) out[idx] = make_float4(0.f, 0.f, 0.f, 0.f);
}

// h = silu(g)*u, fp32 out
__global__ void act_kernel()
{
    size_t idx = (size_t)blockIdx.x * blockDim.x + threadIdx.x;
    if (idx >= (size_t)NASSIGN * IDIM / 4) return;
    size_t r = idx / (IDIM / 4);
    size_t c = (idx % (IDIM / 4)) * 4;
    const float4 g = *(const float4*)(g_gu + r * TWOI + c);
    const float4 u = *(const float4*)(g_gu + r * TWOI + IDIM + c);
    float4 h;
    h.x = g.x / (1.0f + expf(-g.x)) * u.x;
    h.y = g.y / (1.0f + expf(-g.y)) * u.y;
    h.z = g.z / (1.0f + expf(-g.z)) * u.z;
    h.w = g.w / (1.0f + expf(-g.w)) * u.w;
    *(float4*)(g_h + r * IDIM + c) = h;
}

// ============ fused-conversion split-bf16 x3 GEMM ============
// EPI 1: A = Xin gathered by perm tokens, B = w13, out -> g_gu
// EPI 2: A = g_h (permuted rows),          B = w2,  out -> gated atomicAdd
template<int KD, int NTOT, int EPI, int KSPLIT>
__global__ __launch_bounds__(512, 1) void gemm_mma(
    const float* __restrict__ Xin, const float* __restrict__ W, float* __restrict__ outp)
{
    constexpr int NCH = KD / (BK * KSPLIT);

    const int bt    = blockIdx.x;
    const int mrows = g_srows[bt];
    if (mrows == 0) return;
    const int e   = g_se[bt];
    const int m0  = g_sm0[bt];
    const int n0  = blockIdx.y * BN;
    const int kk0 = blockIdx.z * (KD / KSPLIT);

    const float* Bw = W + (size_t)e * NTOT * KD;

    extern __shared__ char smem[];
    const uint32_t sb = smem_to_u32(smem);
    const int tid  = threadIdx.x;
    const int wid  = tid >> 5;
    const int lane = tid & 31;
    const int wm   = (wid & 3) << 5;
    const int wn   = (wid >> 2) << 6;

    // ---- cp.async endpoints (each thread: 2 A chunks, 4 B chunks of 16B) ----
    const float* srcA0; const float* srcA1;
    {
        int r0 = tid >> 3, wg = tid & 7;
        int row0 = m0 + r0, row1 = m0 + r0 + 64;
        if (EPI == 1) {
            int t0 = (row0 < NASSIGN) ? g_perm_token[row0] : 0;
            int t1 = (row1 < NASSIGN) ? g_perm_token[row1] : 0;
            srcA0 = Xin + (size_t)t0 * KD + kk0 + wg * 4;
            srcA1 = Xin + (size_t)t1 * KD + kk0 + wg * 4;
        } else {
            srcA0 = g_h + (size_t)row0 * KD + kk0 + wg * 4;
            srcA1 = g_h + (size_t)row1 * KD + kk0 + wg * 4;
        }
    }
    const float* srcB0 = Bw + (size_t)(n0 + (tid >> 3)) * KD + kk0 + (tid & 7) * 4;
    const uint32_t dA0 = sb + FA_OFF + (tid >> 3) * FPITCHB + (tid & 7) * 16;
    const uint32_t dA1 = dA0 + 64 * FPITCHB;
    const uint32_t dB0 = sb + FB_OFF + (tid >> 3) * FPITCHB + (tid & 7) * 16;

    // ---- ldmatrix per-lane addresses (within bf16 tiles) ----
    const uint32_t a_off = ((wm + (lane & 15)) * PITCH + ((lane >> 4) << 3)) * 2;
    const uint32_t b_off = ((wn + ((lane >> 4) << 3) + (lane & 7)) * PITCH + (((lane >> 3) & 1) << 3)) * 2;

    float acc[2][8][4];
    #pragma unroll
    for (int i = 0; i < 2; i++)
        #pragma unroll
        for (int j = 0; j < 8; j++)
            #pragma unroll
            for (int q = 0; q < 4; q++) acc[i][j][q] = 0.f;

    // prologue: stage 0 fp32 loads
    cp16(dA0, srcA0); cp16(dA1, srcA1);
    cp16(dB0,                  srcB0);
    cp16(dB0 +  64 * FPITCHB,  srcB0 + (size_t) 64 * KD);
    cp16(dB0 + 128 * FPITCHB,  srcB0 + (size_t)128 * KD);
    cp16(dB0 + 192 * FPITCHB,  srcB0 + (size_t)192 * KD);
    asm volatile("cp.async.commit_group;" ::: "memory");
    srcA0 += BK; srcA1 += BK; srcB0 += BK;

    for (int i = 0; i < NCH; i++) {
        asm volatile("cp.async.wait_group 0;" ::: "memory");
        __syncthreads();   // fstage ready; bf16 tiles free (prev ldsm drained)

        // ---- convert fp32 staging -> bf16 hi/lo tiles ----
        {   // A: one (row, kgroup-of-8) per thread
            int r = tid >> 2, kg = tid & 3;
            uint32_t fa = sb + FA_OFF + r * FPITCHB + kg * 32;
            float4 x0, x1; lds128(x0, fa); lds128(x1, fa + 16);
            uint32_t h0,h1,h2,h3,l0,l1,l2,l3;
            split2(x0.x, x0.y, h0, l0); split2(x0.z, x0.w, h1, l1);
            split2(x1.x, x1.y, h2, l2); split2(x1.z, x1.w, h3, l3);
            uint32_t d = sb + AH_OFF + (r * PITCH + kg * 8) * 2;
            sts128(d, h0, h1, h2, h3);
            sts128(d + (AL_OFF - AH_OFF), l0, l1, l2, l3);
        }
        #pragma unroll
        for (int j = 0; j < 2; j++) {   // B: two (row, kgroup) per thread
            int g = tid + j * 512;
            int r = g >> 2, kg = g & 3;
            uint32_t fb = sb + FB_OFF + r * FPITCHB + kg * 32;
            float4 x0, x1; lds128(x0, fb); lds128(x1, fb + 16);
            uint32_t h0,h1,h2,h3,l0,l1,l2,l3;
            split2(x0.x, x0.y, h0, l0); split2(x0.z, x0.w, h1, l1);
            split2(x1.x, x1.y, h2, l2); split2(x1.z, x1.w, h3, l3);
            uint32_t d = sb + BH_OFF + (r * PITCH + kg * 8) * 2;
            sts128(d, h0, h1, h2, h3);
            sts128(d + (BL_OFF - BH_OFF), l0, l1, l2, l3);
        }
        __syncthreads();   // bf16 tiles ready; fstage reads done

        // prefetch next stage fp32 (overlaps with mma below)
        if (i + 1 < NCH) {
            cp16(dA0, srcA0); cp16(dA1, srcA1);
            cp16(dB0,                 srcB0);
            cp16(dB0 +  64 * FPITCHB, srcB0 + (size_t) 64 * KD);
            cp16(dB0 + 128 * FPITCHB, srcB0 + (size_t)128 * KD);
            cp16(dB0 + 192 * FPITCHB, srcB0 + (size_t)192 * KD);
            srcA0 += BK; srcA1 += BK; srcB0 += BK;
        }
        asm volatile("cp.async.commit_group;" ::: "memory");

        // ---- 3-term mma on resident tiles ----
        #pragma unroll
        for (int ks = 0; ks < BK; ks += 16) {
            uint32_t ah[2][4], al[2][4];
            ldsm4(ah[0], sb + AH_OFF + a_off + ks * 2);
            ldsm4(ah[1], sb + AH_OFF + a_off + (16 * PITCH + ks) * 2);
            ldsm4(al[0], sb + AL_OFF + a_off + ks * 2);
            ldsm4(al[1], sb + AL_OFF + a_off + (16 * PITCH + ks) * 2);
            #pragma unroll
            for (int jn = 0; jn < 4; jn++) {   // terms ah*bh + al*bh
                uint32_t bq[4];
                ldsm4(bq, sb + BH_OFF + b_off + (jn * 16 * PITCH + ks) * 2);
                mma16816(acc[0][2*jn],   ah[0], bq);  mma16816(acc[0][2*jn+1], ah[0], bq+2);
                mma16816(acc[1][2*jn],   ah[1], bq);  mma16816(acc[1][2*jn+1], ah[1], bq+2);
                mma16816(acc[0][2*jn],   al[0], bq);  mma16816(acc[0][2*jn+1], al[0], bq+2);
                mma16816(acc[1][2*jn],   al[1], bq);  mma16816(acc[1][2*jn+1], al[1], bq+2);
            }
            #pragma unroll
            for (int jn = 0; jn < 4; jn++) {   // term ah*bl
                uint32_t bq[4];
                ldsm4(bq, sb + BL_OFF + b_off + (jn * 16 * PITCH + ks) * 2);
                mma16816(acc[0][2*jn],   ah[0], bq);  mma16816(acc[0][2*jn+1], ah[0], bq+2);
                mma16816(acc[1][2*jn],   ah[1], bq);  mma16816(acc[1][2*jn+1], ah[1], bq+2);
            }
        }
    }

    // ---------------- epilogue ----------------
    #pragma unroll
    for (int im = 0; im < 2; im++) {
        #pragma unroll
        for (int half = 0; half < 2; half++) {
            const int rloc = wm + im * 16 + half * 8 + (lane >> 2);
            const bool v = (rloc < mrows);
            int tok = 0; float gate = 0.f;
            if (EPI == 2 && v) {
                tok  = g_perm_token[m0 + rloc];
                gate = g_perm_gate[m0 + rloc];
            }
            #pragma unroll
            for (int jn8 = 0; jn8 < 8; jn8++) {
                const float d0 = acc[im][jn8][half * 2 + 0];
                const float d1 = acc[im][jn8][half * 2 + 1];
                const int col = n0 + wn + jn8 * 8 + ((lane & 3) << 1);
                if (v) {
                    if (EPI == 1) {
                        float2* dst = (float2*)(g_gu + (size_t)(m0 + rloc) * TWOI + col);
                        *dst = make_float2(d0, d1);
                    } else {
                        float* dst = outp + (size_t)tok * HDIM + col;
                        atomicAdd(dst + 0, gate * d0);
                        atomicAdd(dst + 1, gate * d1);
                    }
                }
            }
        }
    }
}

// ================= launch =================
extern "C" void kernel_launch(void* const* d_in, const int* in_sizes, int n_in,
                              void* d_out, int out_size)
{
    const float* hs     = (const float*)d_in[0];
    const float* logits = (const float*)d_in[1];
    const float* w13    = (const float*)d_in[2];
    const float* w2     = (const float*)d_in[3];
    float* out = (float*)d_out;

    cudaFuncSetAttribute(gemm_mma<HDIM, TWOI, 1, 1>, cudaFuncAttributeMaxDynamicSharedMemorySize, SMEM_BYTES);
    cudaFuncSetAttribute(gemm_mma<IDIM, HDIM, 2, 4>, cudaFuncAttributeMaxDynamicSharedMemorySize, SMEM_BYTES);

    zero_kernel<<<(T_TOK * HDIM / 4 + 255) / 256, 256>>>((float4*)out);
    route_kernel<<<1, 256>>>(logits);

    gemm_mma<HDIM, TWOI, 1, 1><<<dim3(MAXT, TWOI / BN, 1), 512, SMEM_BYTES>>>(hs, w13, nullptr);

    size_t nact = (size_t)NASSIGN * IDIM / 4;
    act_kernel<<<(unsigned)((nact + 255) / 256), 256>>>();

    gemm_mma<IDIM, HDIM, 2, 4><<<dim3(MAXT, HDIM / BN, 4), 512, SMEM_BYTES>>>(nullptr, w2, out);
}

// round 9
// speedup vs baseline: 3.5321x; 1.4952x over previous
#include <cuda_runtime.h>
#include <cuda_fp16.h>
#include <math.h>
#include <stdint.h>

#define T_TOK   2048
#define HDIM    2048
#define NEXP    8
#define IDIM    5632
#define TWOI    11264
#define NASSIGN 4096
#define MAXT    40
#define PADROWS (NASSIGN + 256)

#define BM 128
#define BN 256
#define BK 32
#define PITCH 40          // fp16 elems per tile row (80B), conflict-free
#define FPITCHB 144       // fp32 staging pitch (bytes)

// GEMM1 smem offsets (bytes)
#define G1_AH 0
#define G1_AL 10240
#define G1_BH 20480
#define G1_FA 40960
#define G1_FB 59392
#define G1_SMEM 96256
// GEMM2 smem offsets
#define G2_AH0 0
#define G2_AH1 10240
#define G2_BH  20480
#define G2_FB  40960
#define G2_SMEM 77824

// ---------------- routing / scheduling state ----------------
__device__ int   g_perm_token[NASSIGN];
__device__ float g_perm_gate[NASSIGN];
__device__ int   g_se[MAXT], g_sm0[MAXT], g_srows[MAXT];

// ---------------- scratch ----------------
__device__ __align__(128) float  g_gu[(size_t)NASSIGN * TWOI];
__device__ __align__(128) __half g_h [(size_t)PADROWS * IDIM];

// ================= helpers =================
__device__ __forceinline__ uint32_t smem_to_u32(const void* p) {
    uint32_t a;
    asm("{ .reg .u64 t; cvta.to.shared.u64 t, %1; cvt.u32.u64 %0, t; }" : "=r"(a) : "l"(p));
    return a;
}
__device__ __forceinline__ void cp16(uint32_t dst, const void* src) {
    asm volatile("cp.async.cg.shared.global [%0], [%1], 16;" :: "r"(dst), "l"(src));
}
__device__ __forceinline__ void ldsm4(uint32_t* r, uint32_t addr) {
    asm volatile("ldmatrix.sync.aligned.m8n8.x4.shared.b16 {%0,%1,%2,%3}, [%4];"
                 : "=r"(r[0]), "=r"(r[1]), "=r"(r[2]), "=r"(r[3]) : "r"(addr));
}
__device__ __forceinline__ void mma16816(float* d, const uint32_t* a, const uint32_t* b) {
    asm volatile(
        "mma.sync.aligned.m16n8k16.row.col.f32.f16.f16.f32 "
        "{%0,%1,%2,%3}, {%4,%5,%6,%7}, {%8,%9}, {%0,%1,%2,%3};"
        : "+f"(d[0]), "+f"(d[1]), "+f"(d[2]), "+f"(d[3])
        : "r"(a[0]), "r"(a[1]), "r"(a[2]), "r"(a[3]), "r"(b[0]), "r"(b[1]));
}
__device__ __forceinline__ void lds128(float4& v, uint32_t a) {
    asm volatile("ld.shared.v4.f32 {%0,%1,%2,%3}, [%4];"
                 : "=f"(v.x), "=f"(v.y), "=f"(v.z), "=f"(v.w) : "r"(a));
}
__device__ __forceinline__ void sts128(uint32_t a, uint32_t x, uint32_t y, uint32_t z, uint32_t w) {
    asm volatile("st.shared.v4.b32 [%0], {%1,%2,%3,%4};" :: "r"(a), "r"(x), "r"(y), "r"(z), "r"(w));
}
// fp32 pair -> fp16x2 hi (packed) + fp16x2 lo (packed)
__device__ __forceinline__ void split2(float f0, float f1, uint32_t& h, uint32_t& l) {
    __half2 hh = __floats2half2_rn(f0, f1);
    float r0 = f0 - __half2float(__low2half(hh));
    float r1 = f1 - __half2float(__high2half(hh));
    __half2 ll = __floats2half2_rn(r0, r1);
    h = *(uint32_t*)&hh; l = *(uint32_t*)&ll;
}
__device__ __forceinline__ uint32_t cvt2(float f0, float f1) {
    __half2 hh = __floats2half2_rn(f0, f1);
    return *(uint32_t*)&hh;
}

// ================= routing =================
__global__ void route_kernel(const float* __restrict__ logits)
{
    __shared__ int s_cnt[NEXP], s_off[NEXP + 1], s_cur[NEXP];
    const int tid = threadIdx.x;
    if (tid < NEXP) s_cnt[tid] = 0;
    __syncthreads();
    for (int t = tid; t < T_TOK; t += blockDim.x) {
        const float* l = logits + t * NEXP;
        int i1 = 0; float v1 = l[0];
        #pragma unroll
        for (int e = 1; e < NEXP; e++) { float v = l[e]; if (v > v1) { v1 = v; i1 = e; } }
        int i2 = -1; float v2 = -3.0e38f;
        #pragma unroll
        for (int e = 0; e < NEXP; e++) { if (e == i1) continue; float v = l[e]; if (v > v2) { v2 = v; i2 = e; } }
        atomicAdd(&s_cnt[i1], 1); atomicAdd(&s_cnt[i2], 1);
    }
    __syncthreads();
    if (tid == 0) {
        int acc = 0;
        for (int e = 0; e < NEXP; e++) { s_off[e] = acc; s_cur[e] = acc; acc += s_cnt[e]; }
        s_off[NEXP] = acc;
    }
    __syncthreads();
    for (int t = tid; t < T_TOK; t += blockDim.x) {
        const float* l = logits + t * NEXP;
        int i1 = 0; float v1 = l[0];
        #pragma unroll
        for (int e = 1; e < NEXP; e++) { float v = l[e]; if (v > v1) { v1 = v; i1 = e; } }
        int i2 = -1; float v2 = -3.0e38f;
        #pragma unroll
        for (int e = 0; e < NEXP; e++) { if (e == i1) continue; float v = l[e]; if (v > v2) { v2 = v; i2 = e; } }
        float g1 = 1.0f / (1.0f + expf(v2 - v1));
        float g2 = 1.0f - g1;
        int s1 = atomicAdd(&s_cur[i1], 1);
        g_perm_token[s1] = t; g_perm_gate[s1] = g1;
        int s2 = atomicAdd(&s_cur[i2], 1);
        g_perm_token[s2] = t; g_perm_gate[s2] = g2;
    }
    __syncthreads();
    if (tid == 0) {
        int nt = 0;
        for (int e = 0; e < NEXP; e++) {
            int off = s_off[e], cnt = s_cnt[e];
            for (int r = 0; r < cnt; r += BM) {
                g_se[nt] = e; g_sm0[nt] = off + r;
                g_srows[nt] = (cnt - r < BM) ? (cnt - r) : BM; nt++;
            }
        }
        for (; nt < MAXT; nt++) g_srows[nt] = 0;
    }
}

__global__ void zero_kernel(float4* __restrict__ out)
{
    int idx = blockIdx.x * blockDim.x + threadIdx.x;
    if (idx < (T_TOK * HDIM) / 4) out[idx] = make_float4(0.f, 0.f, 0.f, 0.f);
}

// h = silu(g)*u, stored as fp16
__global__ void act_kernel()
{
    size_t idx = (size_t)blockIdx.x * blockDim.x + threadIdx.x;
    if (idx >= (size_t)NASSIGN * IDIM / 4) return;
    size_t r = idx / (IDIM / 4);
    size_t c = (idx % (IDIM / 4)) * 4;
    const float4 g = *(const float4*)(g_gu + r * TWOI + c);
    const float4 u = *(const float4*)(g_gu + r * TWOI + IDIM + c);
    float4 h;
    h.x = g.x / (1.0f + expf(-g.x)) * u.x;
    h.y = g.y / (1.0f + expf(-g.y)) * u.y;
    h.z = g.z / (1.0f + expf(-g.z)) * u.z;
    h.w = g.w / (1.0f + expf(-g.w)) * u.w;
    uint2 p;
    p.x = cvt2(h.x, h.y);
    p.y = cvt2(h.z, h.w);
    *(uint2*)(g_h + r * IDIM + c) = p;
}

// ============ GEMM1: A fp32 gathered -> fp16 hi/lo (2 terms), B fp32 -> fp16 ============
__global__ __launch_bounds__(512, 1) void gemm1_mma(
    const float* __restrict__ Xin, const float* __restrict__ W)
{
    constexpr int KD = HDIM, NTOT = TWOI;
    constexpr int NCH = KD / BK;

    const int bt    = blockIdx.x;
    const int mrows = g_srows[bt];
    if (mrows == 0) return;
    const int e  = g_se[bt];
    const int m0 = g_sm0[bt];
    const int n0 = blockIdx.y * BN;
    const float* Bw = W + (size_t)e * NTOT * KD;

    extern __shared__ char smem[];
    const uint32_t sb = smem_to_u32(smem);
    const int tid  = threadIdx.x;
    const int wid  = tid >> 5;
    const int lane = tid & 31;
    const int wm   = (wid & 3) << 5;
    const int wn   = (wid >> 2) << 6;

    // fp32 staging endpoints
    const float* srcA0; const float* srcA1;
    {
        int r0 = tid >> 3, wg = tid & 7;
        int row0 = m0 + r0, row1 = m0 + r0 + 64;
        int t0 = (row0 < NASSIGN) ? g_perm_token[row0] : 0;
        int t1 = (row1 < NASSIGN) ? g_perm_token[row1] : 0;
        srcA0 = Xin + (size_t)t0 * KD + wg * 4;
        srcA1 = Xin + (size_t)t1 * KD + wg * 4;
    }
    const float* srcB0 = Bw + (size_t)(n0 + (tid >> 3)) * KD + (tid & 7) * 4;
    const uint32_t dA0 = sb + G1_FA + (tid >> 3) * FPITCHB + (tid & 7) * 16;
    const uint32_t dA1 = dA0 + 64 * FPITCHB;
    const uint32_t dB0 = sb + G1_FB + (tid >> 3) * FPITCHB + (tid & 7) * 16;

    const uint32_t a_off = ((wm + (lane & 15)) * PITCH + ((lane >> 4) << 3)) * 2;
    const uint32_t b_off = ((wn + ((lane >> 4) << 3) + (lane & 7)) * PITCH + (((lane >> 3) & 1) << 3)) * 2;

    float acc[2][8][4];
    #pragma unroll
    for (int i = 0; i < 2; i++)
        #pragma unroll
        for (int j = 0; j < 8; j++)
            #pragma unroll
            for (int q = 0; q < 4; q++) acc[i][j][q] = 0.f;

    cp16(dA0, srcA0); cp16(dA1, srcA1);
    cp16(dB0,                  srcB0);
    cp16(dB0 +  64 * FPITCHB,  srcB0 + (size_t) 64 * KD);
    cp16(dB0 + 128 * FPITCHB,  srcB0 + (size_t)128 * KD);
    cp16(dB0 + 192 * FPITCHB,  srcB0 + (size_t)192 * KD);
    asm volatile("cp.async.commit_group;" ::: "memory");
    srcA0 += BK; srcA1 += BK; srcB0 += BK;

    for (int i = 0; i < NCH; i++) {
        asm volatile("cp.async.wait_group 0;" ::: "memory");
        __syncthreads();

        {   // A: fp32 -> fp16 hi/lo; one (row, kgroup) per thread
            int r = tid >> 2, kg = tid & 3;
            uint32_t fa = sb + G1_FA + r * FPITCHB + kg * 32;
            float4 x0, x1; lds128(x0, fa); lds128(x1, fa + 16);
            uint32_t h0,h1,h2,h3,l0,l1,l2,l3;
            split2(x0.x, x0.y, h0, l0); split2(x0.z, x0.w, h1, l1);
            split2(x1.x, x1.y, h2, l2); split2(x1.z, x1.w, h3, l3);
            uint32_t d = sb + G1_AH + (r * PITCH + kg * 8) * 2;
            sts128(d, h0, h1, h2, h3);
            sts128(d + (G1_AL - G1_AH), l0, l1, l2, l3);
        }
        #pragma unroll
        for (int j = 0; j < 2; j++) {   // B: fp32 -> fp16 hi; two per thread
            int g = tid + j * 512;
            int r = g >> 2, kg = g & 3;
            uint32_t fb = sb + G1_FB + r * FPITCHB + kg * 32;
            float4 x0, x1; lds128(x0, fb); lds128(x1, fb + 16);
            uint32_t d = sb + G1_BH + (r * PITCH + kg * 8) * 2;
            sts128(d, cvt2(x0.x, x0.y), cvt2(x0.z, x0.w), cvt2(x1.x, x1.y), cvt2(x1.z, x1.w));
        }
        __syncthreads();

        if (i + 1 < NCH) {
            cp16(dA0, srcA0); cp16(dA1, srcA1);
            cp16(dB0,                 srcB0);
            cp16(dB0 +  64 * FPITCHB, srcB0 + (size_t) 64 * KD);
            cp16(dB0 + 128 * FPITCHB, srcB0 + (size_t)128 * KD);
            cp16(dB0 + 192 * FPITCHB, srcB0 + (size_t)192 * KD);
            srcA0 += BK; srcA1 += BK; srcB0 += BK;
        }
        asm volatile("cp.async.commit_group;" ::: "memory");

        #pragma unroll
        for (int ks = 0; ks < BK; ks += 16) {
            uint32_t ah[2][4], al[2][4];
            ldsm4(ah[0], sb + G1_AH + a_off + ks * 2);
            ldsm4(ah[1], sb + G1_AH + a_off + (16 * PITCH + ks) * 2);
            ldsm4(al[0], sb + G1_AL + a_off + ks * 2);
            ldsm4(al[1], sb + G1_AL + a_off + (16 * PITCH + ks) * 2);
            #pragma unroll
            for (int jn = 0; jn < 4; jn++) {
                uint32_t bq[4];
                ldsm4(bq, sb + G1_BH + b_off + (jn * 16 * PITCH + ks) * 2);
                mma16816(acc[0][2*jn],   ah[0], bq);  mma16816(acc[0][2*jn+1], ah[0], bq+2);
                mma16816(acc[1][2*jn],   ah[1], bq);  mma16816(acc[1][2*jn+1], ah[1], bq+2);
                mma16816(acc[0][2*jn],   al[0], bq);  mma16816(acc[0][2*jn+1], al[0], bq+2);
                mma16816(acc[1][2*jn],   al[1], bq);  mma16816(acc[1][2*jn+1], al[1], bq+2);
            }
        }
    }

    // epilogue: write gu fp32
    #pragma unroll
    for (int im = 0; im < 2; im++) {
        #pragma unroll
        for (int half = 0; half < 2; half++) {
            const int rloc = wm + im * 16 + half * 8 + (lane >> 2);
            const bool v = (rloc < mrows);
            #pragma unroll
            for (int jn8 = 0; jn8 < 8; jn8++) {
                if (v) {
                    const int col = n0 + wn + jn8 * 8 + ((lane & 3) << 1);
                    float2* dst = (float2*)(g_gu + (size_t)(m0 + rloc) * TWOI + col);
                    *dst = make_float2(acc[im][jn8][half * 2], acc[im][jn8][half * 2 + 1]);
                }
            }
        }
    }
}

// ============ GEMM2: A fp16 (g_h) direct, B fp32 -> fp16, 1 term, split-K ============
#define KSPLIT2 4
__global__ __launch_bounds__(512, 1) void gemm2_mma(
    const float* __restrict__ W, float* __restrict__ outp)
{
    constexpr int KD = IDIM, NTOT = HDIM;
    constexpr int NCH = KD / (BK * KSPLIT2);

    const int bt    = blockIdx.x;
    const int mrows = g_srows[bt];
    if (mrows == 0) return;
    const int e   = g_se[bt];
    const int m0  = g_sm0[bt];
    const int n0  = blockIdx.y * BN;
    const int kk0 = blockIdx.z * (KD / KSPLIT2);
    const float* Bw = W + (size_t)e * NTOT * KD;

    extern __shared__ char smem[];
    const uint32_t sb = smem_to_u32(smem);
    const int tid  = threadIdx.x;
    const int wid  = tid >> 5;
    const int lane = tid & 31;
    const int wm   = (wid & 3) << 5;
    const int wn   = (wid >> 2) << 6;

    // A: direct fp16 chunk per thread into tile layout
    const __half* srcA = g_h + (size_t)(m0 + (tid >> 2)) * KD + kk0 + (tid & 3) * 8;
    const uint32_t dA  = ((tid >> 2) * PITCH + (tid & 3) * 8) * 2;   // offset within AH buf
    // B fp32 staging
    const float* srcB0 = Bw + (size_t)(n0 + (tid >> 3)) * KD + kk0 + (tid & 7) * 4;
    const uint32_t dB0 = sb + G2_FB + (tid >> 3) * FPITCHB + (tid & 7) * 16;

    const uint32_t a_off = ((wm + (lane & 15)) * PITCH + ((lane >> 4) << 3)) * 2;
    const uint32_t b_off = ((wn + ((lane >> 4) << 3) + (lane & 7)) * PITCH + (((lane >> 3) & 1) << 3)) * 2;

    float acc[2][8][4];
    #pragma unroll
    for (int i = 0; i < 2; i++)
        #pragma unroll
        for (int j = 0; j < 8; j++)
            #pragma unroll
            for (int q = 0; q < 4; q++) acc[i][j][q] = 0.f;

    cp16(sb + G2_AH0 + dA, srcA);
    cp16(dB0,                  srcB0);
    cp16(dB0 +  64 * FPITCHB,  srcB0 + (size_t) 64 * KD);
    cp16(dB0 + 128 * FPITCHB,  srcB0 + (size_t)128 * KD);
    cp16(dB0 + 192 * FPITCHB,  srcB0 + (size_t)192 * KD);
    asm volatile("cp.async.commit_group;" ::: "memory");
    srcA += BK; srcB0 += BK;

    for (int i = 0; i < NCH; i++) {
        const uint32_t ahbuf = sb + ((i & 1) ? G2_AH1 : G2_AH0);
        asm volatile("cp.async.wait_group 0;" ::: "memory");
        __syncthreads();

        #pragma unroll
        for (int j = 0; j < 2; j++) {   // B: fp32 -> fp16
            int g = tid + j * 512;
            int r = g >> 2, kg = g & 3;
            uint32_t fb = sb + G2_FB + r * FPITCHB + kg * 32;
            float4 x0, x1; lds128(x0, fb); lds128(x1, fb + 16);
            uint32_t d = sb + G2_BH + (r * PITCH + kg * 8) * 2;
            sts128(d, cvt2(x0.x, x0.y), cvt2(x0.z, x0.w), cvt2(x1.x, x1.y), cvt2(x1.z, x1.w));
        }
        __syncthreads();

        if (i + 1 < NCH) {
            cp16(sb + (((i + 1) & 1) ? G2_AH1 : G2_AH0) + dA, srcA);
            cp16(dB0,                 srcB0);
            cp16(dB0 +  64 * FPITCHB, srcB0 + (size_t) 64 * KD);
            cp16(dB0 + 128 * FPITCHB, srcB0 + (size_t)128 * KD);
            cp16(dB0 + 192 * FPITCHB, srcB0 + (size_t)192 * KD);
            srcA += BK; srcB0 += BK;
        }
        asm volatile("cp.async.commit_group;" ::: "memory");

        #pragma unroll
        for (int ks = 0; ks < BK; ks += 16) {
            uint32_t ah[2][4];
            ldsm4(ah[0], ahbuf + a_off + ks * 2);
            ldsm4(ah[1], ahbuf + a_off + (16 * PITCH + ks) * 2);
            #pragma unroll
            for (int jn = 0; jn < 4; jn++) {
                uint32_t bq[4];
                ldsm4(bq, sb + G2_BH + b_off + (jn * 16 * PITCH + ks) * 2);
                mma16816(acc[0][2*jn],   ah[0], bq);  mma16816(acc[0][2*jn+1], ah[0], bq+2);
                mma16816(acc[1][2*jn],   ah[1], bq);  mma16816(acc[1][2*jn+1], ah[1], bq+2);
            }
        }
    }

    // epilogue: gated atomic add
    #pragma unroll
    for (int im = 0; im < 2; im++) {
        #pragma unroll
        for (int half = 0; half < 2; half++) {
            const int rloc = wm + im * 16 + half * 8 + (lane >> 2);
            const bool v = (rloc < mrows);
            int tok = 0; float gate = 0.f;
            if (v) { tok = g_perm_token[m0 + rloc]; gate = g_perm_gate[m0 + rloc]; }
            #pragma unroll
            for (int jn8 = 0; jn8 < 8; jn8++) {
                if (v) {
                    const int col = n0 + wn + jn8 * 8 + ((lane & 3) << 1);
                    float* dst = outp + (size_t)tok * HDIM + col;
                    atomicAdd(dst + 0, gate * acc[im][jn8][half * 2 + 0]);
                    atomicAdd(dst + 1, gate * acc[im][jn8][half * 2 + 1]);
                }
            }
        }
    }
}

// ================= launch =================
extern "C" void kernel_launch(void* const* d_in, const int* in_sizes, int n_in,
                              void* d_out, int out_size)
{
    const float* hs     = (const float*)d_in[0];
    const float* logits = (const float*)d_in[1];
    const float* w13    = (const float*)d_in[2];
    const float* w2     = (const float*)d_in[3];
    float* out = (float*)d_out;

    cudaFuncSetAttribute(gemm1_mma, cudaFuncAttributeMaxDynamicSharedMemorySize, G1_SMEM);
    cudaFuncSetAttribute(gemm2_mma, cudaFuncAttributeMaxDynamicSharedMemorySize, G2_SMEM);

    zero_kernel<<<(T_TOK * HDIM / 4 + 255) / 256, 256>>>((float4*)out);
    route_kernel<<<1, 256>>>(logits);

    gemm1_mma<<<dim3(MAXT, TWOI / BN), 512, G1_SMEM>>>(hs, w13);

    size_t nact = (size_t)NASSIGN * IDIM / 4;
    act_kernel<<<(unsigned)((nact + 255) / 256), 256>>>();

    gemm2_mma<<<dim3(MAXT, HDIM / BN, KSPLIT2), 512, G2_SMEM>>>(w2, out);
}

// round 11
// speedup vs baseline: 4.8345x; 1.3687x over previous
#include <cuda_runtime.h>
#include <cuda_fp16.h>
#include <math.h>
#include <stdint.h>

#define T_TOK   2048
#define HDIM    2048
#define NEXP    8
#define IDIM    5632
#define TWOI    11264
#define NASSIGN 4096
#define MAXT    40
#define PADROWS (NASSIGN + 256)

#define BM 128
#define BN 256
#define BK 32
#define PITCH 40                      // fp16 elems per smem row (80B), conflict-free
#define ASZ (BM * PITCH * 2)          // 10240 B
#define BSZ (BN * PITCH * 2)          // 20480 B
#define STAGE (ASZ + BSZ)             // 30720 B
#define SMEM_BYTES (2 * STAGE)        // 61440 B

// ---------------- routing / scheduling state ----------------
__device__ int   g_perm_token[NASSIGN];
__device__ float g_perm_gate[NASSIGN];
__device__ int   g_se[MAXT], g_sm0[MAXT], g_srows[MAXT];

// ---------------- fp16 operands / scratch ----------------
__device__ __align__(128) __half g_af  [(size_t)PADROWS * HDIM];          // gathered X, fp16
__device__ __align__(128) __half g_w13f[(size_t)NEXP * TWOI * HDIM];      // w13 fp16
__device__ __align__(128) __half g_w2f [(size_t)NEXP * HDIM * IDIM];      // w2 fp16
__device__ __align__(128) float  g_gu  [(size_t)NASSIGN * TWOI];
__device__ __align__(128) __half g_h   [(size_t)PADROWS * IDIM];

// ================= helpers =================
__device__ __forceinline__ uint32_t smem_to_u32(const void* p) {
    uint32_t a;
    asm("{ .reg .u64 t; cvta.to.shared.u64 t, %1; cvt.u32.u64 %0, t; }" : "=r"(a) : "l"(p));
    return a;
}
__device__ __forceinline__ void cp16(uint32_t dst, const void* src) {
    asm volatile("cp.async.cg.shared.global [%0], [%1], 16;" :: "r"(dst), "l"(src));
}
__device__ __forceinline__ void ldsm4(uint32_t* r, uint32_t addr) {
    asm volatile("ldmatrix.sync.aligned.m8n8.x4.shared.b16 {%0,%1,%2,%3}, [%4];"
                 : "=r"(r[0]), "=r"(r[1]), "=r"(r[2]), "=r"(r[3]) : "r"(addr));
}
__device__ __forceinline__ void mma16816(float* d, const uint32_t* a, const uint32_t* b) {
    asm volatile(
        "mma.sync.aligned.m16n8k16.row.col.f32.f16.f16.f32 "
        "{%0,%1,%2,%3}, {%4,%5,%6,%7}, {%8,%9}, {%0,%1,%2,%3};"
        : "+f"(d[0]), "+f"(d[1]), "+f"(d[2]), "+f"(d[3])
        : "r"(a[0]), "r"(a[1]), "r"(a[2]), "r"(a[3]), "r"(b[0]), "r"(b[1]));
}
__device__ __forceinline__ uint32_t cvt2(float f0, float f1) {
    __half2 hh = __floats2half2_rn(f0, f1);
    return *(uint32_t*)&hh;
}

// ================= routing =================
__global__ void route_kernel(const float* __restrict__ logits)
{
    __shared__ int s_cnt[NEXP], s_off[NEXP + 1], s_cur[NEXP];
    const int tid = threadIdx.x;
    if (tid < NEXP) s_cnt[tid] = 0;
    __syncthreads();
    for (int t = tid; t < T_TOK; t += blockDim.x) {
        const float* l = logits + t * NEXP;
        int i1 = 0; float v1 = l[0];
        #pragma unroll
        for (int e = 1; e < NEXP; e++) { float v = l[e]; if (v > v1) { v1 = v; i1 = e; } }
        int i2 = -1; float v2 = -3.0e38f;
        #pragma unroll
        for (int e = 0; e < NEXP; e++) { if (e == i1) continue; float v = l[e]; if (v > v2) { v2 = v; i2 = e; } }
        atomicAdd(&s_cnt[i1], 1); atomicAdd(&s_cnt[i2], 1);
    }
    __syncthreads();
    if (tid == 0) {
        int acc = 0;
        for (int e = 0; e < NEXP; e++) { s_off[e] = acc; s_cur[e] = acc; acc += s_cnt[e]; }
        s_off[NEXP] = acc;
    }
    __syncthreads();
    for (int t = tid; t < T_TOK; t += blockDim.x) {
        const float* l = logits + t * NEXP;
        int i1 = 0; float v1 = l[0];
        #pragma unroll
        for (int e = 1; e < NEXP; e++) { float v = l[e]; if (v > v1) { v1 = v; i1 = e; } }
        int i2 = -1; float v2 = -3.0e38f;
        #pragma unroll
        for (int e = 0; e < NEXP; e++) { if (e == i1) continue; float v = l[e]; if (v > v2) { v2 = v; i2 = e; } }
        float g1 = 1.0f / (1.0f + expf(v2 - v1));
        float g2 = 1.0f - g1;
        int s1 = atomicAdd(&s_cur[i1], 1);
        g_perm_token[s1] = t; g_perm_gate[s1] = g1;
        int s2 = atomicAdd(&s_cur[i2], 1);
        g_perm_token[s2] = t; g_perm_gate[s2] = g2;
    }
    __syncthreads();
    if (tid == 0) {
        int nt = 0;
        for (int e = 0; e < NEXP; e++) {
            int off = s_off[e], cnt = s_cnt[e];
            for (int r = 0; r < cnt; r += BM) {
                g_se[nt] = e; g_sm0[nt] = off + r;
                g_srows[nt] = (cnt - r < BM) ? (cnt - r) : BM; nt++;
            }
        }
        for (; nt < MAXT; nt++) g_srows[nt] = 0;
    }
}

__global__ void zero_kernel(float4* __restrict__ out)
{
    int idx = blockIdx.x * blockDim.x + threadIdx.x;
    if (idx < (T_TOK * HDIM) / 4) out[idx] = make_float4(0.f, 0.f, 0.f, 0.f);
}

// gather X rows by perm token, convert to fp16
__global__ void permA_kernel(const float* __restrict__ X)
{
    int idx = blockIdx.x * blockDim.x + threadIdx.x;       // one per 4 elems
    if (idx >= NASSIGN * HDIM / 4) return;
    int r = idx / (HDIM / 4);
    int c = (idx % (HDIM / 4)) * 4;
    int t = g_perm_token[r];
    float4 x = *(const float4*)(X + (size_t)t * HDIM + c);
    uint2 p; p.x = cvt2(x.x, x.y); p.y = cvt2(x.z, x.w);
    *(uint2*)(g_af + (size_t)r * HDIM + c) = p;
}

// flat fp32 -> fp16 weight conversion. WHICH: 0 = w13, 1 = w2.
template<int WHICH>
__global__ void cvt16_kernel(const float4* __restrict__ src, size_t n4)
{
    __half* dst = (WHICH == 0) ? g_w13f : g_w2f;
    size_t idx = (size_t)blockIdx.x * blockDim.x + threadIdx.x;
    if (idx >= n4) return;
    float4 x = src[idx];
    uint2 p; p.x = cvt2(x.x, x.y); p.y = cvt2(x.z, x.w);
    *(uint2*)(dst + idx * 4) = p;
}

// h = silu(g)*u, stored fp16
__global__ void act_kernel()
{
    size_t idx = (size_t)blockIdx.x * blockDim.x + threadIdx.x;
    if (idx >= (size_t)NASSIGN * IDIM / 4) return;
    size_t r = idx / (IDIM / 4);
    size_t c = (idx % (IDIM / 4)) * 4;
    const float4 g = *(const float4*)(g_gu + r * TWOI + c);
    const float4 u = *(const float4*)(g_gu + r * TWOI + IDIM + c);
    float4 h;
    h.x = g.x / (1.0f + expf(-g.x)) * u.x;
    h.y = g.y / (1.0f + expf(-g.y)) * u.y;
    h.z = g.z / (1.0f + expf(-g.z)) * u.z;
    h.w = g.w / (1.0f + expf(-g.w)) * u.w;
    uint2 p; p.x = cvt2(h.x, h.y); p.y = cvt2(h.z, h.w);
    *(uint2*)(g_h + r * IDIM + c) = p;
}

// ============ single-term fp16 GEMM, tiles loaded directly via cp.async ============
__device__ __forceinline__ void load_stage_f16(uint32_t sbase, int tid,
    const __half* __restrict__ A, const __half* __restrict__ B, int KD,
    int m0, int n0, int kk)
{
    {   // A: 128 rows x 32 halfs = 512 x 16B chunks, one per thread
        int row = tid >> 2, kg = tid & 3;
        cp16(sbase + (row * PITCH + kg * 8) * 2,
             A + (size_t)(m0 + row) * KD + kk + kg * 8);
    }
    {   // B: 256 rows x 32 halfs = 1024 chunks, two per thread
        uint32_t bb = sbase + ASZ;
        #pragma unroll
        for (int j = 0; j < 2; j++) {
            int idx = j * 512 + tid;
            int row = idx >> 2, kg = idx & 3;
            cp16(bb + (row * PITCH + kg * 8) * 2,
                 B + (size_t)(n0 + row) * KD + kk + kg * 8);
        }
    }
    asm volatile("cp.async.commit_group;" ::: "memory");
}

// EPI 1: A = g_af, B = g_w13f, out -> g_gu
// EPI 2: A = g_h,  B = g_w2f,  out -> gated atomicAdd
template<int KD, int NTOT, int EPI, int KSPLIT>
__global__ __launch_bounds__(512, 1) void gemm_f16(float* __restrict__ outp)
{
    constexpr int NCH = KD / (BK * KSPLIT);

    const int bt    = blockIdx.x;
    const int mrows = g_srows[bt];
    if (mrows == 0) return;
    const int e   = g_se[bt];
    const int m0  = g_sm0[bt];
    const int n0  = blockIdx.y * BN;
    const int kk0 = blockIdx.z * (KD / KSPLIT);

    const __half* Aopt = (EPI == 1) ? g_af : g_h;
    const __half* Bw   = ((EPI == 1) ? g_w13f : g_w2f) + (size_t)e * NTOT * KD;

    extern __shared__ char smem[];
    const uint32_t sb0 = smem_to_u32(smem);
    const int tid  = threadIdx.x;
    const int wid  = tid >> 5;
    const int lane = tid & 31;
    const int wm   = (wid & 3) << 5;
    const int wn   = (wid >> 2) << 6;

    float acc[2][8][4];
    #pragma unroll
    for (int i = 0; i < 2; i++)
        #pragma unroll
        for (int j = 0; j < 8; j++)
            #pragma unroll
            for (int q = 0; q < 4; q++) acc[i][j][q] = 0.f;

    const uint32_t a_off = ((wm + (lane & 15)) * PITCH + ((lane >> 4) << 3)) * 2;
    const uint32_t b_off = ASZ + ((wn + ((lane >> 4) << 3) + (lane & 7)) * PITCH + (((lane >> 3) & 1) << 3)) * 2;

    load_stage_f16(sb0, tid, Aopt, Bw, KD, m0, n0, kk0);

    for (int i = 0; i < NCH; i++) {
        const int b = i & 1;
        if (i + 1 < NCH) {
            load_stage_f16(sb0 + (1 - b) * STAGE, tid, Aopt, Bw, KD, m0, n0, kk0 + (i + 1) * BK);
            asm volatile("cp.async.wait_group 1;" ::: "memory");
        } else {
            asm volatile("cp.async.wait_group 0;" ::: "memory");
        }
        __syncthreads();

        const uint32_t sa = sb0 + b * STAGE;
        #pragma unroll
        for (int ks = 0; ks < BK; ks += 16) {
            uint32_t afr[2][4], bfr[4][4];
            ldsm4(afr[0], sa + a_off + ks * 2);
            ldsm4(afr[1], sa + a_off + (16 * PITCH + ks) * 2);
            #pragma unroll
            for (int jn = 0; jn < 4; jn++)
                ldsm4(bfr[jn], sa + b_off + (jn * 16 * PITCH + ks) * 2);
            #pragma unroll
            for (int im = 0; im < 2; im++)
                #pragma unroll
                for (int jn = 0; jn < 4; jn++) {
                    mma16816(acc[im][2 * jn],     afr[im], &bfr[jn][0]);
                    mma16816(acc[im][2 * jn + 1], afr[im], &bfr[jn][2]);
                }
        }
        __syncthreads();
    }

    // ---------------- epilogue ----------------
    #pragma unroll
    for (int im = 0; im < 2; im++) {
        #pragma unroll
        for (int half = 0; half < 2; half++) {
            const int rloc = wm + im * 16 + half * 8 + (lane >> 2);
            const bool v = (rloc < mrows);
            int tok = 0; float gate = 0.f;
            if (EPI == 2 && v) {
                tok  = g_perm_token[m0 + rloc];
                gate = g_perm_gate[m0 + rloc];
            }
            #pragma unroll
            for (int jn8 = 0; jn8 < 8; jn8++) {
                const float d0 = acc[im][jn8][half * 2 + 0];
                const float d1 = acc[im][jn8][half * 2 + 1];
                const int col = n0 + wn + jn8 * 8 + ((lane & 3) << 1);
                if (v) {
                    if (EPI == 1) {
                        float2* dst = (float2*)(g_gu + (size_t)(m0 + rloc) * TWOI + col);
                        *dst = make_float2(d0, d1);
                    } else {
                        float* dst = outp + (size_t)tok * HDIM + col;
                        atomicAdd(dst + 0, gate * d0);
                        atomicAdd(dst + 1, gate * d1);
                    }
                }
            }
        }
    }
}

// ================= launch =================
extern "C" void kernel_launch(void* const* d_in, const int* in_sizes, int n_in,
                              void* d_out, int out_size)
{
    const float* hs     = (const float*)d_in[0];
    const float* logits = (const float*)d_in[1];
    const float* w13    = (const float*)d_in[2];
    const float* w2     = (const float*)d_in[3];
    float* out = (float*)d_out;

    cudaFuncSetAttribute(gemm_f16<HDIM, TWOI, 1, 1>, cudaFuncAttributeMaxDynamicSharedMemorySize, SMEM_BYTES);
    cudaFuncSetAttribute(gemm_f16<IDIM, HDIM, 2, 2>, cudaFuncAttributeMaxDynamicSharedMemorySize, SMEM_BYTES);

    zero_kernel<<<(T_TOK * HDIM / 4 + 255) / 256, 256>>>((float4*)out);
    route_kernel<<<1, 256>>>(logits);
    permA_kernel<<<(NASSIGN * HDIM / 4 + 255) / 256, 256>>>(hs);

    size_t n4_w13 = (size_t)NEXP * TWOI * HDIM / 4;
    size_t n4_w2  = (size_t)NEXP * HDIM * IDIM / 4;
    cvt16_kernel<0><<<(unsigned)((n4_w13 + 255) / 256), 256>>>((const float4*)w13, n4_w13);
    cvt16_kernel<1><<<(unsigned)((n4_w2  + 255) / 256), 256>>>((const float4*)w2,  n4_w2);

    gemm_f16<HDIM, TWOI, 1, 1><<<dim3(MAXT, TWOI / BN, 1), 512, SMEM_BYTES>>>(nullptr);

    size_t nact = (size_t)NASSIGN * IDIM / 4;
    act_kernel<<<(unsigned)((nact + 255) / 256), 256>>>();

    gemm_f16<IDIM, HDIM, 2, 2><<<dim3(MAXT, HDIM / BN, 2), 512, SMEM_BYTES>>>(out);
}